// round 5
// baseline (speedup 1.0000x reference)
#include <cuda_runtime.h>
#include <cuda_bf16.h>
#include <stdint.h>

#define NN 100000
#define NP 100096            // NN padded to multiple of 128 (and 64)
#define NE 600000
#define NG 200
#define NL 5
#define OC 10

#define ALPHA_F 0.1f
#define OMA_F 0.9f
#define BETA_F 0.0077821404f
#define OMB_F (1.0f - BETA_F)
#define BN_EPS_F 1e-5f

#define SMS 132              // padded smem row stride (floats) -> conflict-free

#define SCAN_CH 1024
#define NCHUNK ((NN + SCAN_CH - 1) / SCAN_CH)   // 98

// ---------------- scratch (static device globals; zero-initialized) ----------------
__device__ float d_Y[(size_t)NL * NP * 128];      // pre-BN layer outputs Y_0..Y_4
__device__ __nv_bfloat16 d_wt[NL * 128 * 128];    // W transposed [l][n][k] bf16
__device__ int   d_csr_src[NE];
__device__ float d_csr_w[NE];
__device__ int   d_rowptr[NN + 1];
__device__ int   d_cursor[NN];
__device__ int   d_deg_in[NN];
__device__ int   d_deg_out[NN];
__device__ float d_norm_in[NN];
__device__ float d_pooled[(NL + 1) * NG * 128];
__device__ float d_colsum[128];     // zero-init; bnfinal re-zeroes (replay-safe)
__device__ float d_colsumsq[128];
__device__ float d_scale_l[NL * 128];
__device__ float d_shift_l[NL * 128];
__device__ int   d_gstart[NG + 1];
__device__ int   d_chunksum[NCHUNK];

// ---------------- setup kernels ----------------
__global__ void zero_deg_kernel() {
    int n = blockIdx.x * blockDim.x + threadIdx.x;
    if (n < NN) { d_deg_in[n] = 0; d_deg_out[n] = 0; }
}

__global__ void deg_kernel(const int* __restrict__ src, const int* __restrict__ dst) {
    int e = blockIdx.x * blockDim.x + threadIdx.x;
    if (e < NE) {
        atomicAdd(&d_deg_out[src[e]], 1);
        atomicAdd(&d_deg_in[dst[e]], 1);
    }
}

__global__ void norm_kernel() {
    int n = blockIdx.x * blockDim.x + threadIdx.x;
    if (n < NN)
        d_norm_in[n] = rsqrtf(fmaxf((float)d_deg_in[n], 1.0f));
}

__global__ void scan1_kernel() {
    __shared__ int s[SCAN_CH];
    int t = threadIdx.x;
    int idx = blockIdx.x * SCAN_CH + t;
    int v = (idx < NN) ? d_deg_in[idx] : 0;
    s[t] = v;
    __syncthreads();
    for (int off = 1; off < SCAN_CH; off <<= 1) {
        int x = (t >= off) ? s[t - off] : 0;
        __syncthreads();
        s[t] += x;
        __syncthreads();
    }
    if (idx < NN) d_rowptr[idx + 1] = s[t];
    if (t == SCAN_CH - 1) d_chunksum[blockIdx.x] = s[t];
}

__global__ void scan2_kernel() {
    if (threadIdx.x == 0) {
        int run = 0;
        for (int b = 0; b < NCHUNK; ++b) { int t = d_chunksum[b]; d_chunksum[b] = run; run += t; }
    }
}

__global__ void scan3_kernel() {
    int i = blockIdx.x * blockDim.x + threadIdx.x;
    if (i == 0) d_rowptr[0] = 0;
    if (i < NN) d_rowptr[i + 1] += d_chunksum[i >> 10];
}

__global__ void cursor_kernel() {
    int n = blockIdx.x * blockDim.x + threadIdx.x;
    if (n < NN) d_cursor[n] = d_rowptr[n];
}

__global__ void fill_kernel(const int* __restrict__ src, const int* __restrict__ dst) {
    int e = blockIdx.x * blockDim.x + threadIdx.x;
    if (e < NE) {
        int s = src[e];
        int p = atomicAdd(&d_cursor[dst[e]], 1);
        d_csr_src[p] = s;
        d_csr_w[p]   = rsqrtf(fmaxf((float)d_deg_out[s], 1.0f));
    }
}

__global__ void wtconv_kernel(const float* __restrict__ gcn_w) {
    int idx = blockIdx.x * blockDim.x + threadIdx.x;
    if (idx >= NL * 128 * 128) return;
    int l = idx >> 14;
    int rem = idx & 16383;
    int n = rem >> 7;
    int k = rem & 127;
    d_wt[l * 16384 + n * 128 + k] = __float2bfloat16(gcn_w[l * 16384 + k * 128 + n]);
}

__global__ void gstart_kernel(const int* __restrict__ gid) {
    int n = blockIdx.x * blockDim.x + threadIdx.x;
    if (n >= NN) return;
    int gc = gid[n];
    int gp = (n == 0) ? -1 : gid[n - 1];
    for (int g = gp + 1; g <= gc; ++g) d_gstart[g] = n;
    if (n == NN - 1)
        for (int g = gc + 1; g <= NG; ++g) d_gstart[g] = NN;
}

// ---------------- fused layer kernel ----------------
__device__ __forceinline__ void mma_bf16(float c[4], uint32_t a0, uint32_t a1, uint32_t a2,
                                         uint32_t a3, uint32_t b0, uint32_t b1) {
    asm volatile(
        "mma.sync.aligned.m16n8k16.row.col.f32.bf16.bf16.f32 "
        "{%0,%1,%2,%3}, {%4,%5,%6,%7}, {%8,%9}, {%0,%1,%2,%3};\n"
        : "+f"(c[0]), "+f"(c[1]), "+f"(c[2]), "+f"(c[3])
        : "r"(a0), "r"(a1), "r"(a2), "r"(a3), "r"(b0), "r"(b1));
}

__device__ __forceinline__ uint32_t pack_bf16x2(float x, float y) {
    __nv_bfloat162 p = __floats2bfloat162_rn(x, y);
    return *(uint32_t*)&p;
}

// One block: 64 rows. Phase 1 (gather w/ on-the-fly BN+ReLU of prev layer) -> smem rst.
// Phase 2: MMA + epilogue (residual + bias). Stats: shuffle -> smem -> 256 global atomics.
template <bool BN>
__global__ __launch_bounds__(256) void layer_kernel(const float* __restrict__ feat,
                                                    const float* __restrict__ gcn_b,
                                                    int layer) {
    __shared__ float s_rst[64 * SMS];   // 33792 B
    __shared__ float s_stat[256];       // [0:128] colsum, [128:256] colsumsq
    int warp = threadIdx.x >> 5;
    int lane = threadIdx.x & 31;
    int rowbase = blockIdx.x * 64;

    s_stat[threadIdx.x] = 0.f;

    const float* h = BN ? (d_Y + (size_t)(layer - 1) * NP * 128) : feat;
    const float4* h4 = (const float4*)h;

    float4 scv, shv;
    if (BN) {
        scv = ((const float4*)(d_scale_l + (layer - 1) * 128))[lane];
        shv = ((const float4*)(d_shift_l + (layer - 1) * 128))[lane];
    }

#define BNR(v)                                                        \
    if (BN) {                                                         \
        v.x = fmaxf(v.x * scv.x + shv.x, 0.f);                        \
        v.y = fmaxf(v.y * scv.y + shv.y, 0.f);                        \
        v.z = fmaxf(v.z * scv.z + shv.z, 0.f);                        \
        v.w = fmaxf(v.w * scv.w + shv.w, 0.f);                        \
    }

    // ---- gather: warp w handles local rows w*8 .. w*8+7 ----
    // 8-edge round with clamped indices: 8 independent 128-bit loads in flight.
    for (int t = 0; t < 8; ++t) {
        int rl = warp * 8 + t;
        int n = rowbase + rl;
        float4 r = make_float4(0.f, 0.f, 0.f, 0.f);
        if (n < NN) {
            int beg = __ldg(&d_rowptr[n]);
            int end = __ldg(&d_rowptr[n + 1]);
            float4 acc = make_float4(0.f, 0.f, 0.f, 0.f);
            for (int i = beg; i < end; i += 8) {
                int   sIdx[8];
                float wv[8];
                float4 v[8];
#pragma unroll
                for (int k = 0; k < 8; ++k) {
                    int j = min(i + k, end - 1);
                    sIdx[k] = d_csr_src[j];
                    wv[k] = (i + k < end) ? d_csr_w[j] : 0.f;
                }
#pragma unroll
                for (int k = 0; k < 8; ++k)
                    v[k] = h4[(size_t)sIdx[k] * 32 + lane];
#pragma unroll
                for (int k = 0; k < 8; ++k) {
                    BNR(v[k]);
                    acc.x += wv[k] * v[k].x;
                    acc.y += wv[k] * v[k].y;
                    acc.z += wv[k] * v[k].z;
                    acc.w += wv[k] * v[k].w;
                }
            }
            float ni = OMA_F * d_norm_in[n];
            float4 hv = h4[(size_t)n * 32 + lane];
            BNR(hv);
            r.x = ni * acc.x + ALPHA_F * hv.x;
            r.y = ni * acc.y + ALPHA_F * hv.y;
            r.z = ni * acc.z + ALPHA_F * hv.z;
            r.w = ni * acc.w + ALPHA_F * hv.w;
        }
        *(float4*)&s_rst[rl * SMS + lane * 4] = r;
    }
#undef BNR
    __syncthreads();

    // ---- MMA: warp tile = 16 rows x 64 cols ----
    int r0 = (warp & 3) * 16;       // local row tile
    int cb = (warp >> 2) * 64;      // col half
    int qr = lane >> 2;             // 0..7
    int qc = (lane & 3) * 2;        // 0,2,4,6
    const uint32_t* W32 = (const uint32_t*)(d_wt + layer * 16384);  // [n][k] pairs

    float acc[8][4];
#pragma unroll
    for (int nt = 0; nt < 8; ++nt)
#pragma unroll
        for (int j = 0; j < 4; ++j) acc[nt][j] = 0.f;

#pragma unroll
    for (int kk = 0; kk < 8; ++kk) {
        int k0 = kk * 16;
        float2 x;
        x = *(const float2*)&s_rst[(r0 + qr) * SMS + k0 + qc];
        uint32_t a0 = pack_bf16x2(x.x, x.y);
        x = *(const float2*)&s_rst[(r0 + qr + 8) * SMS + k0 + qc];
        uint32_t a1 = pack_bf16x2(x.x, x.y);
        x = *(const float2*)&s_rst[(r0 + qr) * SMS + k0 + 8 + qc];
        uint32_t a2 = pack_bf16x2(x.x, x.y);
        x = *(const float2*)&s_rst[(r0 + qr + 8) * SMS + k0 + 8 + qc];
        uint32_t a3 = pack_bf16x2(x.x, x.y);
#pragma unroll
        for (int nt = 0; nt < 8; ++nt) {
            int n0 = cb + nt * 8;
            uint32_t b0 = W32[(n0 + qr) * 64 + ((k0 + qc) >> 1)];
            uint32_t b1 = W32[(n0 + qr) * 64 + ((k0 + 8 + qc) >> 1)];
            mma_bf16(acc[nt], a0, a1, a2, a3, b0, b1);
        }
    }

    // ---- epilogue: Y = (1-BETA)*rst + BETA*acc + bias ; column stats ----
    float* Y = d_Y + (size_t)layer * NP * 128;
    const float* bias = gcn_b + layer * 128;
    int row1 = rowbase + r0 + qr;
    int row2 = row1 + 8;

#pragma unroll
    for (int nt = 0; nt < 8; ++nt) {
        int col = cb + nt * 8 + qc;
        float bx = bias[col], by = bias[col + 1];
        float s0 = 0.f, s1 = 0.f, q0 = 0.f, q1 = 0.f;
        if (row1 < NN) {
            float2 x = *(const float2*)&s_rst[(r0 + qr) * SMS + col];
            float2 o;
            o.x = OMB_F * x.x + BETA_F * acc[nt][0] + bx;
            o.y = OMB_F * x.y + BETA_F * acc[nt][1] + by;
            *(float2*)&Y[(size_t)row1 * 128 + col] = o;
            s0 += o.x; s1 += o.y; q0 += o.x * o.x; q1 += o.y * o.y;
        }
        if (row2 < NN) {
            float2 x = *(const float2*)&s_rst[(r0 + qr + 8) * SMS + col];
            float2 o;
            o.x = OMB_F * x.x + BETA_F * acc[nt][2] + bx;
            o.y = OMB_F * x.y + BETA_F * acc[nt][3] + by;
            *(float2*)&Y[(size_t)row2 * 128 + col] = o;
            s0 += o.x; s1 += o.y; q0 += o.x * o.x; q1 += o.y * o.y;
        }
        // reduce over qr (lane bits 2..4)
#pragma unroll
        for (int m = 4; m <= 16; m <<= 1) {
            s0 += __shfl_xor_sync(0xffffffffu, s0, m);
            s1 += __shfl_xor_sync(0xffffffffu, s1, m);
            q0 += __shfl_xor_sync(0xffffffffu, q0, m);
            q1 += __shfl_xor_sync(0xffffffffu, q1, m);
        }
        if (lane < 4) {
            atomicAdd(&s_stat[col], s0);
            atomicAdd(&s_stat[col + 1], s1);
            atomicAdd(&s_stat[128 + col], q0);
            atomicAdd(&s_stat[128 + col + 1], q1);
        }
    }

    __syncthreads();
    // one global atomic per (stat, col) per block
    int t = threadIdx.x;
    float v = s_stat[t];
    if (t < 128)
        atomicAdd(&d_colsum[t], v);
    else
        atomicAdd(&d_colsumsq[t - 128], v);
}

// compute per-layer BN scale/shift; re-zero stats for next layer / next replay
__global__ void bnfinal_kernel(const float* __restrict__ bn_g, const float* __restrict__ bn_b,
                               int layer) {
    int d = threadIdx.x;
    float mu = d_colsum[d] * (1.0f / NN);
    float var = d_colsumsq[d] * (1.0f / NN) - mu * mu;
    float sc = bn_g[layer * 128 + d] * rsqrtf(var + BN_EPS_F);
    d_scale_l[layer * 128 + d] = sc;
    d_shift_l[layer * 128 + d] = bn_b[layer * 128 + d] - mu * sc;
    d_colsum[d] = 0.f;
    d_colsumsq[d] = 0.f;
}

// ---------------- readout ----------------
__global__ __launch_bounds__(128) void pool_kernel(const float* __restrict__ feat) {
    int l = blockIdx.x / NG;
    int g = blockIdx.x % NG;
    const float* hp = (l == 0) ? feat : (d_Y + (size_t)(l - 1) * NP * 128);
    int d = threadIdx.x;
    bool bn = (l > 0);
    float sc = 1.f, sh = 0.f;
    if (bn) {
        sc = d_scale_l[(l - 1) * 128 + d];
        sh = d_shift_l[(l - 1) * 128 + d];
    }
    int s = d_gstart[g], e = d_gstart[g + 1];
    // 8 independent accumulator chains -> 8 loads in flight
    float a0 = 0.f, a1 = 0.f, a2 = 0.f, a3 = 0.f;
    float a4 = 0.f, a5 = 0.f, a6 = 0.f, a7 = 0.f;
    int n = s;
#define PL(idx, aa)                                                    \
    {                                                                  \
        float v = hp[(size_t)(n + idx) * 128 + d];                     \
        if (bn) v = fmaxf(v * sc + sh, 0.f);                           \
        aa += v;                                                       \
    }
    for (; n + 7 < e; n += 8) {
        PL(0, a0) PL(1, a1) PL(2, a2) PL(3, a3)
        PL(4, a4) PL(5, a5) PL(6, a6) PL(7, a7)
    }
    for (; n < e; ++n) PL(0, a0)
#undef PL
    float acc = ((a0 + a1) + (a2 + a3)) + ((a4 + a5) + (a6 + a7));
    d_pooled[(l * NG + g) * 128 + d] = acc;
}

__global__ __launch_bounds__(128) void score_kernel(const float* __restrict__ lin_w,
                                                    const float* __restrict__ lin_b,
                                                    float* __restrict__ out) {
    int g = blockIdx.x;
    int t = threadIdx.x;
    __shared__ float sc[OC];
    __shared__ float s_lse;
    if (t < OC) {
        float b = 0.f;
        for (int i = 0; i <= NL; ++i) b += lin_b[i * OC + t];
        sc[t] = b;
    }
    __syncthreads();
    float part[OC];
#pragma unroll
    for (int o = 0; o < OC; ++o) part[o] = 0.f;
    for (int i = 0; i <= NL; ++i) {
        float p = d_pooled[(i * NG + g) * 128 + t];
        const float* w = lin_w + i * 128 * OC + t * OC;
#pragma unroll
        for (int o = 0; o < OC; ++o) part[o] += p * w[o];
    }
#pragma unroll
    for (int o = 0; o < OC; ++o) atomicAdd(&sc[o], part[o]);
    __syncthreads();
    if (t == 0) {
        float m = sc[0];
        for (int o = 1; o < OC; ++o) m = fmaxf(m, sc[o]);
        float se = 0.f;
        for (int o = 0; o < OC; ++o) se += expf(sc[o] - m);
        s_lse = logf(se) + m;
    }
    __syncthreads();
    if (t < OC) out[g * OC + t] = sc[t] - s_lse;
}

__global__ void mean_kernel(float* __restrict__ out) {
    int idx = blockIdx.x * blockDim.x + threadIdx.x;
    if (idx >= NG * 128) return;
    int g = idx >> 7;
    int d = idx & 127;
    float s = 0.f;
    for (int i = 1; i <= NL; ++i) s += d_pooled[(i * NG + g) * 128 + d];
    out[NG * OC + idx] = s * 0.2f;
}

// ---------------- launch ----------------
extern "C" void kernel_launch(void* const* d_in, const int* in_sizes, int n_in,
                              void* d_out, int out_size) {
    const float* feat  = (const float*)d_in[0];
    const int*   src   = (const int*)d_in[1];
    const int*   dst   = (const int*)d_in[2];
    const int*   gid   = (const int*)d_in[3];
    const float* gcn_w = (const float*)d_in[4];
    const float* gcn_b = (const float*)d_in[5];
    const float* bn_g  = (const float*)d_in[6];
    const float* bn_b  = (const float*)d_in[7];
    const float* lin_w = (const float*)d_in[8];
    const float* lin_b = (const float*)d_in[9];
    float* out = (float*)d_out;

    const int NB_N = (NN + 255) / 256;   // 391
    const int NB_E = (NE + 255) / 256;   // 2344

    zero_deg_kernel<<<NB_N, 256>>>();
    deg_kernel<<<NB_E, 256>>>(src, dst);
    norm_kernel<<<NB_N, 256>>>();
    scan1_kernel<<<NCHUNK, SCAN_CH>>>();
    scan2_kernel<<<1, 32>>>();
    scan3_kernel<<<NB_N, 256>>>();
    cursor_kernel<<<NB_N, 256>>>();
    fill_kernel<<<NB_E, 256>>>(src, dst);
    wtconv_kernel<<<(NL * 128 * 128 + 255) / 256, 256>>>(gcn_w);
    gstart_kernel<<<NB_N, 256>>>(gid);

    for (int l = 0; l < NL; ++l) {
        if (l == 0)
            layer_kernel<false><<<NP / 64, 256>>>(feat, gcn_b, l);
        else
            layer_kernel<true><<<NP / 64, 256>>>(feat, gcn_b, l);
        bnfinal_kernel<<<1, 128>>>(bn_g, bn_b, l);
    }

    pool_kernel<<<(NL + 1) * NG, 128>>>(feat);
    score_kernel<<<NG, 128>>>(lin_w, lin_b, out);
    mean_kernel<<<(NG * 128 + 255) / 256, 256>>>(out);
}

// round 6
// speedup vs baseline: 1.0018x; 1.0018x over previous
#include <cuda_runtime.h>
#include <cuda_bf16.h>
#include <stdint.h>

#define NN 100000
#define NP 100096            // NN padded to multiple of 128 (and 64)
#define NE 600000
#define NG 200
#define NL 5
#define OC 10

#define ALPHA_F 0.1f
#define OMA_F 0.9f
#define BETA_F 0.0077821404f
#define OMB_F (1.0f - BETA_F)
#define BN_EPS_F 1e-5f

#define SMS 132              // padded smem row stride (floats) -> conflict-free

#define SCAN_CH 1024
#define NCHUNK ((NN + SCAN_CH - 1) / SCAN_CH)   // 98

// ---------------- scratch (static device globals; zero-initialized) ----------------
__device__ float d_Y[(size_t)NL * NP * 128];      // pre-BN layer outputs Y_0..Y_4
__device__ __nv_bfloat16 d_wt[NL * 128 * 128];    // W transposed [l][n][k] bf16
__device__ int   d_csr_src[NE];
__device__ float d_csr_w[NE];
__device__ int   d_rowptr[NN + 1];
__device__ int   d_cursor[NN];
__device__ int   d_deg_in[NN];
__device__ int   d_deg_out[NN];
__device__ float d_norm_in[NN];
__device__ float d_pooled[(NL + 1) * NG * 128];
__device__ float d_colsum[128];     // zero-init; bnfinal re-zeroes (replay-safe)
__device__ float d_colsumsq[128];
__device__ float d_scale_l[NL * 128];
__device__ float d_shift_l[NL * 128];
__device__ int   d_gstart[NG + 1];
__device__ int   d_chunksum[NCHUNK];

// ---------------- setup kernels ----------------
__global__ void zero_deg_kernel() {
    int n = blockIdx.x * blockDim.x + threadIdx.x;
    if (n < NN) { d_deg_in[n] = 0; d_deg_out[n] = 0; }
}

__global__ void deg_kernel(const int* __restrict__ src, const int* __restrict__ dst) {
    int e = blockIdx.x * blockDim.x + threadIdx.x;
    if (e < NE) {
        atomicAdd(&d_deg_out[src[e]], 1);
        atomicAdd(&d_deg_in[dst[e]], 1);
    }
}

__global__ void norm_kernel() {
    int n = blockIdx.x * blockDim.x + threadIdx.x;
    if (n < NN)
        d_norm_in[n] = rsqrtf(fmaxf((float)d_deg_in[n], 1.0f));
}

__global__ void scan1_kernel() {
    __shared__ int s[SCAN_CH];
    int t = threadIdx.x;
    int idx = blockIdx.x * SCAN_CH + t;
    int v = (idx < NN) ? d_deg_in[idx] : 0;
    s[t] = v;
    __syncthreads();
    for (int off = 1; off < SCAN_CH; off <<= 1) {
        int x = (t >= off) ? s[t - off] : 0;
        __syncthreads();
        s[t] += x;
        __syncthreads();
    }
    if (idx < NN) d_rowptr[idx + 1] = s[t];
    if (t == SCAN_CH - 1) d_chunksum[blockIdx.x] = s[t];
}

__global__ void scan2_kernel() {
    if (threadIdx.x == 0) {
        int run = 0;
        for (int b = 0; b < NCHUNK; ++b) { int t = d_chunksum[b]; d_chunksum[b] = run; run += t; }
    }
}

__global__ void scan3_kernel() {
    int i = blockIdx.x * blockDim.x + threadIdx.x;
    if (i == 0) d_rowptr[0] = 0;
    if (i < NN) d_rowptr[i + 1] += d_chunksum[i >> 10];
}

__global__ void cursor_kernel() {
    int n = blockIdx.x * blockDim.x + threadIdx.x;
    if (n < NN) d_cursor[n] = d_rowptr[n];
}

__global__ void fill_kernel(const int* __restrict__ src, const int* __restrict__ dst) {
    int e = blockIdx.x * blockDim.x + threadIdx.x;
    if (e < NE) {
        int s = src[e];
        int p = atomicAdd(&d_cursor[dst[e]], 1);
        d_csr_src[p] = s;
        d_csr_w[p]   = rsqrtf(fmaxf((float)d_deg_out[s], 1.0f));
    }
}

__global__ void wtconv_kernel(const float* __restrict__ gcn_w) {
    int idx = blockIdx.x * blockDim.x + threadIdx.x;
    if (idx >= NL * 128 * 128) return;
    int l = idx >> 14;
    int rem = idx & 16383;
    int n = rem >> 7;
    int k = rem & 127;
    d_wt[l * 16384 + n * 128 + k] = __float2bfloat16(gcn_w[l * 16384 + k * 128 + n]);
}

__global__ void gstart_kernel(const int* __restrict__ gid) {
    int n = blockIdx.x * blockDim.x + threadIdx.x;
    if (n >= NN) return;
    int gc = gid[n];
    int gp = (n == 0) ? -1 : gid[n - 1];
    for (int g = gp + 1; g <= gc; ++g) d_gstart[g] = n;
    if (n == NN - 1)
        for (int g = gc + 1; g <= NG; ++g) d_gstart[g] = NN;
}

// ---------------- fused layer kernel ----------------
__device__ __forceinline__ void mma_bf16(float c[4], uint32_t a0, uint32_t a1, uint32_t a2,
                                         uint32_t a3, uint32_t b0, uint32_t b1) {
    asm volatile(
        "mma.sync.aligned.m16n8k16.row.col.f32.bf16.bf16.f32 "
        "{%0,%1,%2,%3}, {%4,%5,%6,%7}, {%8,%9}, {%0,%1,%2,%3};\n"
        : "+f"(c[0]), "+f"(c[1]), "+f"(c[2]), "+f"(c[3])
        : "r"(a0), "r"(a1), "r"(a2), "r"(a3), "r"(b0), "r"(b1));
}

__device__ __forceinline__ uint32_t pack_bf16x2(float x, float y) {
    __nv_bfloat162 p = __floats2bfloat162_rn(x, y);
    return *(uint32_t*)&p;
}

// One block: 64 rows. Phase 1 (gather w/ on-the-fly BN+ReLU of prev layer) -> smem rst.
// Phase 2: MMA + epilogue (residual + bias). Stats: shuffle -> smem -> 256 global atomics.
template <bool BN>
__global__ __launch_bounds__(256) void layer_kernel(const float* __restrict__ feat,
                                                    const float* __restrict__ gcn_b,
                                                    int layer) {
    __shared__ float s_rst[64 * SMS];   // 33792 B
    __shared__ float s_stat[256];       // [0:128] colsum, [128:256] colsumsq
    int warp = threadIdx.x >> 5;
    int lane = threadIdx.x & 31;
    int rowbase = blockIdx.x * 64;

    s_stat[threadIdx.x] = 0.f;

    const float* h = BN ? (d_Y + (size_t)(layer - 1) * NP * 128) : feat;
    const float4* h4 = (const float4*)h;

    float4 scv, shv;
    if (BN) {
        scv = ((const float4*)(d_scale_l + (layer - 1) * 128))[lane];
        shv = ((const float4*)(d_shift_l + (layer - 1) * 128))[lane];
    }

#define BNR(v)                                                        \
    if (BN) {                                                         \
        v.x = fmaxf(v.x * scv.x + shv.x, 0.f);                        \
        v.y = fmaxf(v.y * scv.y + shv.y, 0.f);                        \
        v.z = fmaxf(v.z * scv.z + shv.z, 0.f);                        \
        v.w = fmaxf(v.w * scv.w + shv.w, 0.f);                        \
    }

    // ---- gather: warp w handles local rows w*8 .. w*8+7 ----
    // 8-edge round with clamped indices: 8 independent 128-bit loads in flight.
    for (int t = 0; t < 8; ++t) {
        int rl = warp * 8 + t;
        int n = rowbase + rl;
        float4 r = make_float4(0.f, 0.f, 0.f, 0.f);
        if (n < NN) {
            int beg = __ldg(&d_rowptr[n]);
            int end = __ldg(&d_rowptr[n + 1]);
            float4 acc = make_float4(0.f, 0.f, 0.f, 0.f);
            for (int i = beg; i < end; i += 8) {
                int   sIdx[8];
                float wv[8];
                float4 v[8];
#pragma unroll
                for (int k = 0; k < 8; ++k) {
                    int j = min(i + k, end - 1);
                    sIdx[k] = d_csr_src[j];
                    wv[k] = (i + k < end) ? d_csr_w[j] : 0.f;
                }
#pragma unroll
                for (int k = 0; k < 8; ++k)
                    v[k] = h4[(size_t)sIdx[k] * 32 + lane];
#pragma unroll
                for (int k = 0; k < 8; ++k) {
                    BNR(v[k]);
                    acc.x += wv[k] * v[k].x;
                    acc.y += wv[k] * v[k].y;
                    acc.z += wv[k] * v[k].z;
                    acc.w += wv[k] * v[k].w;
                }
            }
            float ni = OMA_F * d_norm_in[n];
            float4 hv = h4[(size_t)n * 32 + lane];
            BNR(hv);
            r.x = ni * acc.x + ALPHA_F * hv.x;
            r.y = ni * acc.y + ALPHA_F * hv.y;
            r.z = ni * acc.z + ALPHA_F * hv.z;
            r.w = ni * acc.w + ALPHA_F * hv.w;
        }
        *(float4*)&s_rst[rl * SMS + lane * 4] = r;
    }
#undef BNR
    __syncthreads();

    // ---- MMA: warp tile = 16 rows x 64 cols ----
    int r0 = (warp & 3) * 16;       // local row tile
    int cb = (warp >> 2) * 64;      // col half
    int qr = lane >> 2;             // 0..7
    int qc = (lane & 3) * 2;        // 0,2,4,6
    const uint32_t* W32 = (const uint32_t*)(d_wt + layer * 16384);  // [n][k] pairs

    float acc[8][4];
#pragma unroll
    for (int nt = 0; nt < 8; ++nt)
#pragma unroll
        for (int j = 0; j < 4; ++j) acc[nt][j] = 0.f;

#pragma unroll
    for (int kk = 0; kk < 8; ++kk) {
        int k0 = kk * 16;
        float2 x;
        x = *(const float2*)&s_rst[(r0 + qr) * SMS + k0 + qc];
        uint32_t a0 = pack_bf16x2(x.x, x.y);
        x = *(const float2*)&s_rst[(r0 + qr + 8) * SMS + k0 + qc];
        uint32_t a1 = pack_bf16x2(x.x, x.y);
        x = *(const float2*)&s_rst[(r0 + qr) * SMS + k0 + 8 + qc];
        uint32_t a2 = pack_bf16x2(x.x, x.y);
        x = *(const float2*)&s_rst[(r0 + qr + 8) * SMS + k0 + 8 + qc];
        uint32_t a3 = pack_bf16x2(x.x, x.y);
#pragma unroll
        for (int nt = 0; nt < 8; ++nt) {
            int n0 = cb + nt * 8;
            uint32_t b0 = W32[(n0 + qr) * 64 + ((k0 + qc) >> 1)];
            uint32_t b1 = W32[(n0 + qr) * 64 + ((k0 + 8 + qc) >> 1)];
            mma_bf16(acc[nt], a0, a1, a2, a3, b0, b1);
        }
    }

    // ---- epilogue: Y = (1-BETA)*rst + BETA*acc + bias ; column stats ----
    float* Y = d_Y + (size_t)layer * NP * 128;
    const float* bias = gcn_b + layer * 128;
    int row1 = rowbase + r0 + qr;
    int row2 = row1 + 8;

#pragma unroll
    for (int nt = 0; nt < 8; ++nt) {
        int col = cb + nt * 8 + qc;
        float bx = bias[col], by = bias[col + 1];
        float s0 = 0.f, s1 = 0.f, q0 = 0.f, q1 = 0.f;
        if (row1 < NN) {
            float2 x = *(const float2*)&s_rst[(r0 + qr) * SMS + col];
            float2 o;
            o.x = OMB_F * x.x + BETA_F * acc[nt][0] + bx;
            o.y = OMB_F * x.y + BETA_F * acc[nt][1] + by;
            *(float2*)&Y[(size_t)row1 * 128 + col] = o;
            s0 += o.x; s1 += o.y; q0 += o.x * o.x; q1 += o.y * o.y;
        }
        if (row2 < NN) {
            float2 x = *(const float2*)&s_rst[(r0 + qr + 8) * SMS + col];
            float2 o;
            o.x = OMB_F * x.x + BETA_F * acc[nt][2] + bx;
            o.y = OMB_F * x.y + BETA_F * acc[nt][3] + by;
            *(float2*)&Y[(size_t)row2 * 128 + col] = o;
            s0 += o.x; s1 += o.y; q0 += o.x * o.x; q1 += o.y * o.y;
        }
        // reduce over qr (lane bits 2..4)
#pragma unroll
        for (int m = 4; m <= 16; m <<= 1) {
            s0 += __shfl_xor_sync(0xffffffffu, s0, m);
            s1 += __shfl_xor_sync(0xffffffffu, s1, m);
            q0 += __shfl_xor_sync(0xffffffffu, q0, m);
            q1 += __shfl_xor_sync(0xffffffffu, q1, m);
        }
        if (lane < 4) {
            atomicAdd(&s_stat[col], s0);
            atomicAdd(&s_stat[col + 1], s1);
            atomicAdd(&s_stat[128 + col], q0);
            atomicAdd(&s_stat[128 + col + 1], q1);
        }
    }

    __syncthreads();
    // one global atomic per (stat, col) per block
    int t = threadIdx.x;
    float v = s_stat[t];
    if (t < 128)
        atomicAdd(&d_colsum[t], v);
    else
        atomicAdd(&d_colsumsq[t - 128], v);
}

// compute per-layer BN scale/shift; re-zero stats for next layer / next replay
__global__ void bnfinal_kernel(const float* __restrict__ bn_g, const float* __restrict__ bn_b,
                               int layer) {
    int d = threadIdx.x;
    float mu = d_colsum[d] * (1.0f / NN);
    float var = d_colsumsq[d] * (1.0f / NN) - mu * mu;
    float sc = bn_g[layer * 128 + d] * rsqrtf(var + BN_EPS_F);
    d_scale_l[layer * 128 + d] = sc;
    d_shift_l[layer * 128 + d] = bn_b[layer * 128 + d] - mu * sc;
    d_colsum[d] = 0.f;
    d_colsumsq[d] = 0.f;
}

// ---------------- readout ----------------
__global__ __launch_bounds__(128) void pool_kernel(const float* __restrict__ feat) {
    int l = blockIdx.x / NG;
    int g = blockIdx.x % NG;
    const float* hp = (l == 0) ? feat : (d_Y + (size_t)(l - 1) * NP * 128);
    int d = threadIdx.x;
    bool bn = (l > 0);
    float sc = 1.f, sh = 0.f;
    if (bn) {
        sc = d_scale_l[(l - 1) * 128 + d];
        sh = d_shift_l[(l - 1) * 128 + d];
    }
    int s = d_gstart[g], e = d_gstart[g + 1];
    // 8 independent accumulator chains -> 8 loads in flight
    float a0 = 0.f, a1 = 0.f, a2 = 0.f, a3 = 0.f;
    float a4 = 0.f, a5 = 0.f, a6 = 0.f, a7 = 0.f;
    int n = s;
#define PL(idx, aa)                                                    \
    {                                                                  \
        float v = hp[(size_t)(n + idx) * 128 + d];                     \
        if (bn) v = fmaxf(v * sc + sh, 0.f);                           \
        aa += v;                                                       \
    }
    for (; n + 7 < e; n += 8) {
        PL(0, a0) PL(1, a1) PL(2, a2) PL(3, a3)
        PL(4, a4) PL(5, a5) PL(6, a6) PL(7, a7)
    }
    for (; n < e; ++n) PL(0, a0)
#undef PL
    float acc = ((a0 + a1) + (a2 + a3)) + ((a4 + a5) + (a6 + a7));
    d_pooled[(l * NG + g) * 128 + d] = acc;
}

__global__ __launch_bounds__(128) void score_kernel(const float* __restrict__ lin_w,
                                                    const float* __restrict__ lin_b,
                                                    float* __restrict__ out) {
    int g = blockIdx.x;
    int t = threadIdx.x;
    __shared__ float sc[OC];
    __shared__ float s_lse;
    if (t < OC) {
        float b = 0.f;
        for (int i = 0; i <= NL; ++i) b += lin_b[i * OC + t];
        sc[t] = b;
    }
    __syncthreads();
    float part[OC];
#pragma unroll
    for (int o = 0; o < OC; ++o) part[o] = 0.f;
    for (int i = 0; i <= NL; ++i) {
        float p = d_pooled[(i * NG + g) * 128 + t];
        const float* w = lin_w + i * 128 * OC + t * OC;
#pragma unroll
        for (int o = 0; o < OC; ++o) part[o] += p * w[o];
    }
#pragma unroll
    for (int o = 0; o < OC; ++o) atomicAdd(&sc[o], part[o]);
    __syncthreads();
    if (t == 0) {
        float m = sc[0];
        for (int o = 1; o < OC; ++o) m = fmaxf(m, sc[o]);
        float se = 0.f;
        for (int o = 0; o < OC; ++o) se += expf(sc[o] - m);
        s_lse = logf(se) + m;
    }
    __syncthreads();
    if (t < OC) out[g * OC + t] = sc[t] - s_lse;
}

__global__ void mean_kernel(float* __restrict__ out) {
    int idx = blockIdx.x * blockDim.x + threadIdx.x;
    if (idx >= NG * 128) return;
    int g = idx >> 7;
    int d = idx & 127;
    float s = 0.f;
    for (int i = 1; i <= NL; ++i) s += d_pooled[(i * NG + g) * 128 + d];
    out[NG * OC + idx] = s * 0.2f;
}

// ---------------- launch ----------------
extern "C" void kernel_launch(void* const* d_in, const int* in_sizes, int n_in,
                              void* d_out, int out_size) {
    const float* feat  = (const float*)d_in[0];
    const int*   src   = (const int*)d_in[1];
    const int*   dst   = (const int*)d_in[2];
    const int*   gid   = (const int*)d_in[3];
    const float* gcn_w = (const float*)d_in[4];
    const float* gcn_b = (const float*)d_in[5];
    const float* bn_g  = (const float*)d_in[6];
    const float* bn_b  = (const float*)d_in[7];
    const float* lin_w = (const float*)d_in[8];
    const float* lin_b = (const float*)d_in[9];
    float* out = (float*)d_out;

    const int NB_N = (NN + 255) / 256;   // 391
    const int NB_E = (NE + 255) / 256;   // 2344

    zero_deg_kernel<<<NB_N, 256>>>();
    deg_kernel<<<NB_E, 256>>>(src, dst);
    norm_kernel<<<NB_N, 256>>>();
    scan1_kernel<<<NCHUNK, SCAN_CH>>>();
    scan2_kernel<<<1, 32>>>();
    scan3_kernel<<<NB_N, 256>>>();
    cursor_kernel<<<NB_N, 256>>>();
    fill_kernel<<<NB_E, 256>>>(src, dst);
    wtconv_kernel<<<(NL * 128 * 128 + 255) / 256, 256>>>(gcn_w);
    gstart_kernel<<<NB_N, 256>>>(gid);

    for (int l = 0; l < NL; ++l) {
        if (l == 0)
            layer_kernel<false><<<NP / 64, 256>>>(feat, gcn_b, l);
        else
            layer_kernel<true><<<NP / 64, 256>>>(feat, gcn_b, l);
        bnfinal_kernel<<<1, 128>>>(bn_g, bn_b, l);
    }

    pool_kernel<<<(NL + 1) * NG, 128>>>(feat);
    score_kernel<<<NG, 128>>>(lin_w, lin_b, out);
    mean_kernel<<<(NG * 128 + 255) / 256, 256>>>(out);
}

// round 7
// speedup vs baseline: 1.1120x; 1.1100x over previous
#include <cuda_runtime.h>
#include <cuda_fp16.h>
#include <stdint.h>

#define NN 100000
#define NP 100096            // NN padded to multiple of 128 (and 64)
#define NE 600000
#define NG 200
#define NL 5
#define OC 10

#define ALPHA_F 0.1f
#define OMA_F 0.9f
#define BETA_F 0.0077821404f
#define OMB_F (1.0f - BETA_F)
#define BN_EPS_F 1e-5f

#define SMS 132              // padded smem row stride (floats) -> conflict-free

#define SCAN_CH 1024
#define NCHUNK ((NN + SCAN_CH - 1) / SCAN_CH)   // 98

// ---------------- scratch (static device globals; zero-initialized) ----------------
__device__ __half d_Yh[(size_t)NL * NP * 128];    // pre-BN layer outputs Y_0..Y_4 (fp16)
__device__ __half d_wt[NL * 128 * 128];           // W transposed [l][n][k] fp16
__device__ int   d_csr_src[NE];
__device__ float d_csr_w[NE];
__device__ int   d_rowptr[NN + 1];
__device__ int   d_cursor[NN];
__device__ int   d_deg_in[NN];
__device__ int   d_deg_out[NN];
__device__ float d_norm_in[NN];
__device__ float d_pooled[(NL + 1) * NG * 128];
__device__ float d_colsum[NL * 128];    // per-layer column sums (zeroed each call)
__device__ float d_colsumsq[NL * 128];
__device__ int   d_gstart[NG + 1];
__device__ int   d_chunksum[NCHUNK];

// ---------------- setup kernels ----------------
__global__ void zero_kernel() {
    int i = blockIdx.x * blockDim.x + threadIdx.x;
    if (i < NN) { d_deg_in[i] = 0; d_deg_out[i] = 0; }
    if (i < (NL + 1) * NG * 128) d_pooled[i] = 0.f;
    if (i < NL * 128) { d_colsum[i] = 0.f; d_colsumsq[i] = 0.f; }
}

__global__ void deg_kernel(const int* __restrict__ src, const int* __restrict__ dst) {
    int e = blockIdx.x * blockDim.x + threadIdx.x;
    if (e < NE) {
        atomicAdd(&d_deg_out[src[e]], 1);
        atomicAdd(&d_deg_in[dst[e]], 1);
    }
}

__global__ void norm_kernel() {
    int n = blockIdx.x * blockDim.x + threadIdx.x;
    if (n < NN)
        d_norm_in[n] = rsqrtf(fmaxf((float)d_deg_in[n], 1.0f));
}

__global__ void scan1_kernel() {
    __shared__ int s[SCAN_CH];
    int t = threadIdx.x;
    int idx = blockIdx.x * SCAN_CH + t;
    int v = (idx < NN) ? d_deg_in[idx] : 0;
    s[t] = v;
    __syncthreads();
    for (int off = 1; off < SCAN_CH; off <<= 1) {
        int x = (t >= off) ? s[t - off] : 0;
        __syncthreads();
        s[t] += x;
        __syncthreads();
    }
    if (idx < NN) d_rowptr[idx + 1] = s[t];
    if (t == SCAN_CH - 1) d_chunksum[blockIdx.x] = s[t];
}

__global__ void scan2_kernel() {
    if (threadIdx.x == 0) {
        int run = 0;
        for (int b = 0; b < NCHUNK; ++b) { int t = d_chunksum[b]; d_chunksum[b] = run; run += t; }
    }
}

__global__ void scan3_kernel() {
    int i = blockIdx.x * blockDim.x + threadIdx.x;
    if (i == 0) d_rowptr[0] = 0;
    if (i < NN) d_rowptr[i + 1] += d_chunksum[i >> 10];
}

__global__ void cursor_kernel() {
    int n = blockIdx.x * blockDim.x + threadIdx.x;
    if (n < NN) d_cursor[n] = d_rowptr[n];
}

__global__ void fill_kernel(const int* __restrict__ src, const int* __restrict__ dst) {
    int e = blockIdx.x * blockDim.x + threadIdx.x;
    if (e < NE) {
        int s = src[e];
        int p = atomicAdd(&d_cursor[dst[e]], 1);
        d_csr_src[p] = s;
        d_csr_w[p]   = rsqrtf(fmaxf((float)d_deg_out[s], 1.0f));
    }
}

__global__ void wtconv_kernel(const float* __restrict__ gcn_w) {
    int idx = blockIdx.x * blockDim.x + threadIdx.x;
    if (idx >= NL * 128 * 128) return;
    int l = idx >> 14;
    int rem = idx & 16383;
    int n = rem >> 7;
    int k = rem & 127;
    d_wt[l * 16384 + n * 128 + k] = __float2half(gcn_w[l * 16384 + k * 128 + n]);
}

__global__ void gstart_kernel(const int* __restrict__ gid) {
    int n = blockIdx.x * blockDim.x + threadIdx.x;
    if (n >= NN) return;
    int gc = gid[n];
    int gp = (n == 0) ? -1 : gid[n - 1];
    for (int g = gp + 1; g <= gc; ++g) d_gstart[g] = n;
    if (n == NN - 1)
        for (int g = gc + 1; g <= NG; ++g) d_gstart[g] = NN;
}

// ---------------- fused layer kernel ----------------
__device__ __forceinline__ void mma_f16(float c[4], uint32_t a0, uint32_t a1, uint32_t a2,
                                        uint32_t a3, uint32_t b0, uint32_t b1) {
    asm volatile(
        "mma.sync.aligned.m16n8k16.row.col.f32.f16.f16.f32 "
        "{%0,%1,%2,%3}, {%4,%5,%6,%7}, {%8,%9}, {%0,%1,%2,%3};\n"
        : "+f"(c[0]), "+f"(c[1]), "+f"(c[2]), "+f"(c[3])
        : "r"(a0), "r"(a1), "r"(a2), "r"(a3), "r"(b0), "r"(b1));
}

__device__ __forceinline__ uint32_t pack_h16x2(float x, float y) {
    __half2 p = __floats2half2_rn(x, y);
    return *(uint32_t*)&p;
}

__device__ __forceinline__ float4 load_h16(const __half* hbase, int node, int lane) {
    uint2 raw = *(const uint2*)(hbase + (size_t)node * 128 + lane * 4);
    __half2 p0 = *(__half2*)&raw.x;
    __half2 p1 = *(__half2*)&raw.y;
    float2 f0 = __half22float2(p0);
    float2 f1 = __half22float2(p1);
    return make_float4(f0.x, f0.y, f1.x, f1.y);
}

// One block: 64 rows.
//  - BN path: block computes BN scale/shift of prev layer from d_colsum[l-1] (complete
//    thanks to kernel boundary), applies BN+ReLU on the fly.
//  - Gather -> smem rst (fp32). Self-read also accumulates pooled[layer] (graph-sorted rows).
//  - f16 MMA + epilogue (residual + bias), Y stored fp16, column stats -> d_colsum[layer].
template <bool BN>
__global__ __launch_bounds__(256) void layer_kernel(const float* __restrict__ feat,
                                                    const int* __restrict__ gid,
                                                    const float* __restrict__ gcn_b,
                                                    const float* __restrict__ bn_g,
                                                    const float* __restrict__ bn_b,
                                                    int layer) {
    __shared__ float s_rst[64 * SMS];   // 33792 B
    __shared__ float s_stat[256];       // [0:128] colsum, [128:256] colsumsq
    __shared__ float s_scale[128];
    __shared__ float s_shift[128];
    int tid = threadIdx.x;
    int warp = tid >> 5;
    int lane = tid & 31;
    int rowbase = blockIdx.x * 64;

    s_stat[tid] = 0.f;
    if (BN && tid < 128) {
        float mu = d_colsum[(layer - 1) * 128 + tid] * (1.0f / NN);
        float var = d_colsumsq[(layer - 1) * 128 + tid] * (1.0f / NN) - mu * mu;
        float sc = bn_g[(layer - 1) * 128 + tid] * rsqrtf(var + BN_EPS_F);
        s_scale[tid] = sc;
        s_shift[tid] = bn_b[(layer - 1) * 128 + tid] - mu * sc;
    }
    __syncthreads();

    const __half* hb = d_Yh + (BN ? (size_t)(layer - 1) * NP * 128 : 0);
    const float4* f4 = (const float4*)feat;

    float4 scv, shv;
    if (BN) {
        scv = ((const float4*)s_scale)[lane];
        shv = ((const float4*)s_shift)[lane];
    }

#define BNR(v)                                                        \
    if (BN) {                                                         \
        v.x = fmaxf(v.x * scv.x + shv.x, 0.f);                        \
        v.y = fmaxf(v.y * scv.y + shv.y, 0.f);                        \
        v.z = fmaxf(v.z * scv.z + shv.z, 0.f);                        \
        v.w = fmaxf(v.w * scv.w + shv.w, 0.f);                        \
    }

    // ---- gather + pooled[layer] accumulation via self-read ----
    int cur_g = -1;
    float4 pacc = make_float4(0.f, 0.f, 0.f, 0.f);
#define PFLUSH()                                                                   \
    if (cur_g >= 0) {                                                              \
        float* dp = d_pooled + ((size_t)layer * NG + cur_g) * 128 + lane * 4;      \
        atomicAdd(dp + 0, pacc.x);                                                 \
        atomicAdd(dp + 1, pacc.y);                                                 \
        atomicAdd(dp + 2, pacc.z);                                                 \
        atomicAdd(dp + 3, pacc.w);                                                 \
    }

    for (int t = 0; t < 8; ++t) {
        int rl = warp * 8 + t;
        int n = rowbase + rl;
        float4 r = make_float4(0.f, 0.f, 0.f, 0.f);
        if (n < NN) {
            int beg = __ldg(&d_rowptr[n]);
            int end = __ldg(&d_rowptr[n + 1]);
            float4 acc = make_float4(0.f, 0.f, 0.f, 0.f);
            for (int i = beg; i < end; i += 8) {
                int   sIdx[8];
                float wv[8];
                float4 v[8];
#pragma unroll
                for (int k = 0; k < 8; ++k) {
                    int j = min(i + k, end - 1);
                    sIdx[k] = d_csr_src[j];
                    wv[k] = (i + k < end) ? d_csr_w[j] : 0.f;
                }
#pragma unroll
                for (int k = 0; k < 8; ++k) {
                    if (BN)
                        v[k] = load_h16(hb, sIdx[k], lane);
                    else
                        v[k] = f4[(size_t)sIdx[k] * 32 + lane];
                }
#pragma unroll
                for (int k = 0; k < 8; ++k) {
                    BNR(v[k]);
                    acc.x += wv[k] * v[k].x;
                    acc.y += wv[k] * v[k].y;
                    acc.z += wv[k] * v[k].z;
                    acc.w += wv[k] * v[k].w;
                }
            }
            float4 hv = BN ? load_h16(hb, n, lane) : f4[(size_t)n * 32 + lane];
            BNR(hv);
            // pooled accumulation (rows are sorted by graph id)
            int g = __ldg(&gid[n]);
            if (g != cur_g) {
                PFLUSH();
                cur_g = g;
                pacc = make_float4(0.f, 0.f, 0.f, 0.f);
            }
            pacc.x += hv.x; pacc.y += hv.y; pacc.z += hv.z; pacc.w += hv.w;

            float ni = OMA_F * d_norm_in[n];
            r.x = ni * acc.x + ALPHA_F * hv.x;
            r.y = ni * acc.y + ALPHA_F * hv.y;
            r.z = ni * acc.z + ALPHA_F * hv.z;
            r.w = ni * acc.w + ALPHA_F * hv.w;
        }
        *(float4*)&s_rst[rl * SMS + lane * 4] = r;
    }
    PFLUSH();
#undef PFLUSH
#undef BNR
    __syncthreads();

    // ---- MMA: warp tile = 16 rows x 64 cols ----
    int r0 = (warp & 3) * 16;       // local row tile
    int cb = (warp >> 2) * 64;      // col half
    int qr = lane >> 2;             // 0..7
    int qc = (lane & 3) * 2;        // 0,2,4,6
    const uint32_t* W32 = (const uint32_t*)(d_wt + layer * 16384);  // [n][k] pairs

    float acc[8][4];
#pragma unroll
    for (int nt = 0; nt < 8; ++nt)
#pragma unroll
        for (int j = 0; j < 4; ++j) acc[nt][j] = 0.f;

#pragma unroll
    for (int kk = 0; kk < 8; ++kk) {
        int k0 = kk * 16;
        float2 x;
        x = *(const float2*)&s_rst[(r0 + qr) * SMS + k0 + qc];
        uint32_t a0 = pack_h16x2(x.x, x.y);
        x = *(const float2*)&s_rst[(r0 + qr + 8) * SMS + k0 + qc];
        uint32_t a1 = pack_h16x2(x.x, x.y);
        x = *(const float2*)&s_rst[(r0 + qr) * SMS + k0 + 8 + qc];
        uint32_t a2 = pack_h16x2(x.x, x.y);
        x = *(const float2*)&s_rst[(r0 + qr + 8) * SMS + k0 + 8 + qc];
        uint32_t a3 = pack_h16x2(x.x, x.y);
#pragma unroll
        for (int nt = 0; nt < 8; ++nt) {
            int n0 = cb + nt * 8;
            uint32_t b0 = W32[(n0 + qr) * 64 + ((k0 + qc) >> 1)];
            uint32_t b1 = W32[(n0 + qr) * 64 + ((k0 + 8 + qc) >> 1)];
            mma_f16(acc[nt], a0, a1, a2, a3, b0, b1);
        }
    }

    // ---- epilogue: Y = (1-BETA)*rst + BETA*acc + bias (fp16 store) ; column stats ----
    __half* Y = d_Yh + (size_t)layer * NP * 128;
    const float* bias = gcn_b + layer * 128;
    int row1 = rowbase + r0 + qr;
    int row2 = row1 + 8;

#pragma unroll
    for (int nt = 0; nt < 8; ++nt) {
        int col = cb + nt * 8 + qc;
        float bx = bias[col], by = bias[col + 1];
        float s0 = 0.f, s1 = 0.f, q0 = 0.f, q1 = 0.f;
        if (row1 < NN) {
            float2 x = *(const float2*)&s_rst[(r0 + qr) * SMS + col];
            float ox = OMB_F * x.x + BETA_F * acc[nt][0] + bx;
            float oy = OMB_F * x.y + BETA_F * acc[nt][1] + by;
            *(__half2*)&Y[(size_t)row1 * 128 + col] = __floats2half2_rn(ox, oy);
            s0 += ox; s1 += oy; q0 += ox * ox; q1 += oy * oy;
        }
        if (row2 < NN) {
            float2 x = *(const float2*)&s_rst[(r0 + qr + 8) * SMS + col];
            float ox = OMB_F * x.x + BETA_F * acc[nt][2] + bx;
            float oy = OMB_F * x.y + BETA_F * acc[nt][3] + by;
            *(__half2*)&Y[(size_t)row2 * 128 + col] = __floats2half2_rn(ox, oy);
            s0 += ox; s1 += oy; q0 += ox * ox; q1 += oy * oy;
        }
        // reduce over qr (lane bits 2..4)
#pragma unroll
        for (int m = 4; m <= 16; m <<= 1) {
            s0 += __shfl_xor_sync(0xffffffffu, s0, m);
            s1 += __shfl_xor_sync(0xffffffffu, s1, m);
            q0 += __shfl_xor_sync(0xffffffffu, q0, m);
            q1 += __shfl_xor_sync(0xffffffffu, q1, m);
        }
        if (lane < 4) {
            atomicAdd(&s_stat[col], s0);
            atomicAdd(&s_stat[col + 1], s1);
            atomicAdd(&s_stat[128 + col], q0);
            atomicAdd(&s_stat[128 + col + 1], q1);
        }
    }

    __syncthreads();
    // one global atomic per (stat, col) per block
    float v = s_stat[tid];
    if (tid < 128)
        atomicAdd(&d_colsum[layer * 128 + tid], v);
    else
        atomicAdd(&d_colsumsq[layer * 128 + tid - 128], v);
}

// ---------------- readout ----------------
// pooled[NL] = per-graph sum of BN(Y_{NL-1}) with ReLU
__global__ __launch_bounds__(128) void pool_last_kernel(const float* __restrict__ bn_g,
                                                        const float* __restrict__ bn_b) {
    int g = blockIdx.x;
    int d = threadIdx.x;
    float mu = d_colsum[(NL - 1) * 128 + d] * (1.0f / NN);
    float var = d_colsumsq[(NL - 1) * 128 + d] * (1.0f / NN) - mu * mu;
    float sc = bn_g[(NL - 1) * 128 + d] * rsqrtf(var + BN_EPS_F);
    float sh = bn_b[(NL - 1) * 128 + d] - mu * sc;
    const __half* Yh = d_Yh + (size_t)(NL - 1) * NP * 128;
    int s = d_gstart[g], e = d_gstart[g + 1];
    float a0 = 0.f, a1 = 0.f, a2 = 0.f, a3 = 0.f;
    float a4 = 0.f, a5 = 0.f, a6 = 0.f, a7 = 0.f;
    int n = s;
#define PL(idx, aa)                                                    \
    {                                                                  \
        float v = __half2float(Yh[(size_t)(n + idx) * 128 + d]);       \
        aa += fmaxf(v * sc + sh, 0.f);                                 \
    }
    for (; n + 7 < e; n += 8) {
        PL(0, a0) PL(1, a1) PL(2, a2) PL(3, a3)
        PL(4, a4) PL(5, a5) PL(6, a6) PL(7, a7)
    }
    for (; n < e; ++n) PL(0, a0)
#undef PL
    float acc = ((a0 + a1) + (a2 + a3)) + ((a4 + a5) + (a6 + a7));
    d_pooled[(NL * NG + g) * 128 + d] = acc;
}

__global__ __launch_bounds__(128) void score_kernel(const float* __restrict__ lin_w,
                                                    const float* __restrict__ lin_b,
                                                    float* __restrict__ out) {
    int g = blockIdx.x;
    int t = threadIdx.x;
    __shared__ float sc[OC];
    __shared__ float s_lse;
    if (t < OC) {
        float b = 0.f;
        for (int i = 0; i <= NL; ++i) b += lin_b[i * OC + t];
        sc[t] = b;
    }
    __syncthreads();
    float part[OC];
#pragma unroll
    for (int o = 0; o < OC; ++o) part[o] = 0.f;
    for (int i = 0; i <= NL; ++i) {
        float p = d_pooled[(i * NG + g) * 128 + t];
        const float* w = lin_w + i * 128 * OC + t * OC;
#pragma unroll
        for (int o = 0; o < OC; ++o) part[o] += p * w[o];
    }
#pragma unroll
    for (int o = 0; o < OC; ++o) atomicAdd(&sc[o], part[o]);
    __syncthreads();
    if (t == 0) {
        float m = sc[0];
        for (int o = 1; o < OC; ++o) m = fmaxf(m, sc[o]);
        float se = 0.f;
        for (int o = 0; o < OC; ++o) se += expf(sc[o] - m);
        s_lse = logf(se) + m;
    }
    __syncthreads();
    if (t < OC) out[g * OC + t] = sc[t] - s_lse;
}

__global__ void mean_kernel(float* __restrict__ out) {
    int idx = blockIdx.x * blockDim.x + threadIdx.x;
    if (idx >= NG * 128) return;
    int g = idx >> 7;
    int d = idx & 127;
    float s = 0.f;
    for (int i = 1; i <= NL; ++i) s += d_pooled[(i * NG + g) * 128 + d];
    out[NG * OC + idx] = s * 0.2f;
}

// ---------------- launch ----------------
extern "C" void kernel_launch(void* const* d_in, const int* in_sizes, int n_in,
                              void* d_out, int out_size) {
    const float* feat  = (const float*)d_in[0];
    const int*   src   = (const int*)d_in[1];
    const int*   dst   = (const int*)d_in[2];
    const int*   gid   = (const int*)d_in[3];
    const float* gcn_w = (const float*)d_in[4];
    const float* gcn_b = (const float*)d_in[5];
    const float* bn_g  = (const float*)d_in[6];
    const float* bn_b  = (const float*)d_in[7];
    const float* lin_w = (const float*)d_in[8];
    const float* lin_b = (const float*)d_in[9];
    float* out = (float*)d_out;

    const int NB_N = (NN + 255) / 256;   // 391
    const int NB_E = (NE + 255) / 256;   // 2344
    const int NB_Z = ((NL + 1) * NG * 128 + 255) / 256;  // 600 (covers NN too)

    zero_kernel<<<NB_Z, 256>>>();
    deg_kernel<<<NB_E, 256>>>(src, dst);
    norm_kernel<<<NB_N, 256>>>();
    scan1_kernel<<<NCHUNK, SCAN_CH>>>();
    scan2_kernel<<<1, 32>>>();
    scan3_kernel<<<NB_N, 256>>>();
    cursor_kernel<<<NB_N, 256>>>();
    fill_kernel<<<NB_E, 256>>>(src, dst);
    wtconv_kernel<<<(NL * 128 * 128 + 255) / 256, 256>>>(gcn_w);
    gstart_kernel<<<NB_N, 256>>>(gid);

    for (int l = 0; l < NL; ++l) {
        if (l == 0)
            layer_kernel<false><<<NP / 64, 256>>>(feat, gid, gcn_b, bn_g, bn_b, l);
        else
            layer_kernel<true><<<NP / 64, 256>>>(feat, gid, gcn_b, bn_g, bn_b, l);
    }

    pool_last_kernel<<<NG, 128>>>(bn_g, bn_b);
    score_kernel<<<NG, 128>>>(lin_w, lin_b, out);
    mean_kernel<<<(NG * 128 + 255) / 256, 256>>>(out);
}